// round 1
// baseline (speedup 1.0000x reference)
#include <cuda_runtime.h>
#include <cstdint>

#define NB 4
#define NP 8192
#define ND 512
#define NS1 4096
#define NS2 2048
#define ROWS_PER_B (NP + NS1 + NS2)   /* 14336 */
#define OUTX_ELEMS ((size_t)NB * ROWS_PER_B * ND)

// FPS indices scratch (device global: no allocations allowed)
__device__ int g_fps_idx[NB * NS1];

// ---- packed f32x2 helpers (Blackwell sm_103a) ----
__device__ __forceinline__ unsigned long long f32x2_add(unsigned long long a, unsigned long long b) {
    unsigned long long r;
    asm("add.rn.f32x2 %0, %1, %2;" : "=l"(r) : "l"(a), "l"(b));
    return r;
}
__device__ __forceinline__ unsigned long long f32x2_mul(unsigned long long a, unsigned long long b) {
    unsigned long long r;
    asm("mul.rn.f32x2 %0, %1, %2;" : "=l"(r) : "l"(a), "l"(b));
    return r;
}
__device__ __forceinline__ unsigned long long pack2(float lo, float hi) {
    unsigned long long r;
    asm("mov.b64 %0, {%1, %2};" : "=l"(r) : "f"(lo), "f"(hi));
    return r;
}
__device__ __forceinline__ void unpack2(unsigned long long v, float& lo, float& hi) {
    asm("mov.b64 {%0, %1}, %2;" : "=f"(lo), "=f"(hi) : "l"(v));
}

// ============================================================================
// FPS: one CTA (1024 threads) per batch. Points held in registers (8/thread,
// packed f32x2 pairs). pos mirrored in SMEM for centroid broadcast via LDS.
// Exactly matches JAX arithmetic: d = ((dx*dx)+(dy*dy))+(dz*dz), each op RN,
// no FMA contraction; dist = min(dist, d); argmax = first occurrence of max.
// One __syncthreads per step; warp candidates double-buffered.
// ============================================================================
__global__ void __launch_bounds__(1024, 1) fps_kernel(const float* __restrict__ pos)
{
    const int b    = blockIdx.x;
    const int tid  = threadIdx.x;
    const int lane = tid & 31;
    const int wid  = tid >> 5;

    extern __shared__ float smem[];
    float* sx = smem;
    float* sy = smem + NP;
    float* sz = smem + 2 * NP;
    uint2* cand = reinterpret_cast<uint2*>(smem + 3 * NP);   // [2][32]

    // Stage pos for this batch into SMEM (one-time)
    const float* pb = pos + (size_t)b * NP * 3;
    for (int i = tid; i < NP; i += 1024) {
        sx[i] = pb[3 * i + 0];
        sy[i] = pb[3 * i + 1];
        sz[i] = pb[3 * i + 2];
    }
    __syncthreads();

    // Thread-private points: contiguous ids [base, base+8) -> lane/warp order
    // is monotone in point index (required for first-occurrence tie-breaking).
    const int base = tid << 3;
    unsigned long long px2[4], py2[4], pz2[4];
    float dist[8];
#pragma unroll
    for (int k = 0; k < 4; k++) {
        px2[k] = pack2(sx[base + 2 * k], sx[base + 2 * k + 1]);
        py2[k] = pack2(sy[base + 2 * k], sy[base + 2 * k + 1]);
        pz2[k] = pack2(sz[base + 2 * k], sz[base + 2 * k + 1]);
    }
#pragma unroll
    for (int j = 0; j < 8; j++) dist[j] = 1e10f;

    int cur = 0;                       // deterministic start at index 0
    if (tid == 0) g_fps_idx[b * NS1] = 0;

    for (int s = 1; s < NS1; s++) {
        const float cx = sx[cur], cy = sy[cur], cz = sz[cur];  // LDS broadcast
        const unsigned long long ncx = pack2(-cx, -cx);
        const unsigned long long ncy = pack2(-cy, -cy);
        const unsigned long long ncz = pack2(-cz, -cz);

        float best  = -1.0f;
        int   besti = base;
#pragma unroll
        for (int k = 0; k < 4; k++) {
            // p + (-c) == p - c exactly (IEEE RN); mul/add separate roundings
            const unsigned long long dx = f32x2_add(px2[k], ncx);
            const unsigned long long dy = f32x2_add(py2[k], ncy);
            const unsigned long long dz = f32x2_add(pz2[k], ncz);
            const unsigned long long qx = f32x2_mul(dx, dx);
            const unsigned long long qy = f32x2_mul(dy, dy);
            const unsigned long long qz = f32x2_mul(dz, dz);
            const unsigned long long sm = f32x2_add(f32x2_add(qx, qy), qz);
            float d0, d1;
            unpack2(sm, d0, d1);
            const float n0 = fminf(dist[2 * k], d0);
            dist[2 * k] = n0;
            if (n0 > best) { best = n0; besti = base + 2 * k; }       // strict > : first max
            const float n1 = fminf(dist[2 * k + 1], d1);
            dist[2 * k + 1] = n1;
            if (n1 > best) { best = n1; besti = base + 2 * k + 1; }
        }

        // Warp argmax: dist >= 0 so float bits are order-preserving as u32.
        const unsigned vb  = __float_as_uint(best);
        const unsigned m   = __reduce_max_sync(0xffffffffu, vb);
        const unsigned bal = __ballot_sync(0xffffffffu, vb == m);
        const int src = __ffs(bal) - 1;                 // lowest lane = lowest idx
        const int wi  = __shfl_sync(0xffffffffu, besti, src);
        if (lane == 0) cand[((s & 1) << 5) + wid] = make_uint2(m, (unsigned)wi);
        __syncthreads();

        // Every warp redundantly reduces the 32 warp candidates (no 2nd barrier).
        const uint2 c2 = cand[((s & 1) << 5) + lane];
        const unsigned m2   = __reduce_max_sync(0xffffffffu, c2.x);
        const unsigned bal2 = __ballot_sync(0xffffffffu, c2.x == m2);
        const int src2 = __ffs(bal2) - 1;               // lowest warp = lowest idx
        cur = __shfl_sync(0xffffffffu, (int)c2.y, src2);
        if (tid == 0) g_fps_idx[b * NS1 + s] = cur;
    }
}

// ============================================================================
// Gather: one 128-thread block per output row; each thread moves one float4
// (512 floats/row). Scale 1.0 rows are a straight copy; 0.5 rows use FPS idx;
// 0.25 rows reuse the first 2048 FPS idx (greedy prefix property).
// Threads 0..2 also emit the 3-float pos row.
// ============================================================================
__global__ void gather_kernel(const float* __restrict__ x,
                              const float* __restrict__ pos,
                              float* __restrict__ outx,
                              float* __restrict__ outp)
{
    const int r = blockIdx.x;
    const int b = r / ROWS_PER_B;
    const int o = r - b * ROWS_PER_B;

    int src;
    if (o < NP)             src = o;
    else if (o < NP + NS1)  src = g_fps_idx[b * NS1 + (o - NP)];
    else                    src = g_fps_idx[b * NS1 + (o - NP - NS1)];

    const size_t srow = (size_t)b * NP + (size_t)src;
    const float4* xin = reinterpret_cast<const float4*>(x + srow * ND);
    float4*       xo  = reinterpret_cast<float4*>(outx + (size_t)r * ND);
    xo[threadIdx.x] = xin[threadIdx.x];                 // 128 x float4 = 512 floats

    if (threadIdx.x < 3)
        outp[(size_t)r * 3 + threadIdx.x] = pos[srow * 3 + threadIdx.x];
}

extern "C" void kernel_launch(void* const* d_in, const int* in_sizes, int n_in,
                              void* d_out, int out_size)
{
    const float* x   = (const float*)d_in[0];   // [B*P, D] f32
    const float* pos = (const float*)d_in[1];   // [B*P, 3] f32
    // d_in[2] = batch_idx (int64, sorted equal-sized) -> implied by reshape

    float* outx = (float*)d_out;                // fused_x: [B*14336, 512]
    float* outp = outx + OUTX_ELEMS;            // fused_p: [B*14336, 3]

    const size_t smem_bytes = (size_t)3 * NP * sizeof(float) + 64 * sizeof(uint2);
    cudaFuncSetAttribute(fps_kernel, cudaFuncAttributeMaxDynamicSharedMemorySize,
                         (int)smem_bytes);

    fps_kernel<<<NB, 1024, smem_bytes>>>(pos);
    gather_kernel<<<NB * ROWS_PER_B, 128>>>(x, pos, outx, outp);
}